// round 2
// baseline (speedup 1.0000x reference)
#include <cuda_runtime.h>

// ---------------- problem constants ----------------
#define B_GRAPHS 2048
#define E        256
#define QKV3     768
#define H        4
#define HD       64
#define DM       128
#define DX       128
#define NMAX     (2048*80)     // counts in [20,81) -> max 80/graph
#define LMAX     128
#define CMAX     80            // max nodes per graph
#define KST      65            // smem row stride (conflict-free: 65 mod 32 = 1)

// ---------------- device scratch (static, allocation-free) ----------------
__device__ int   g_is64;
__device__ int   g_counts[B_GRAPHS];
__device__ int   g_offsets[B_GRAPHS];
__device__ int   g_colcnt[LMAX];
__device__ int   g_colprefix[LMAX];
__device__ int   g_rowrank[LMAX * B_GRAPHS];
__device__ int   g_dest[NMAX];
__device__ float g_qkv[(size_t)NMAX * QKV3];   // ~503 MB
__device__ float g_ctx[(size_t)NMAX * E];      // ~168 MB
__device__ float g_W2[E * E];
__device__ float g_b2[E];

__device__ __forceinline__ int get_batch(const void* b, int i) {
    if (g_is64) return (int)((const long long*)b)[i];
    return ((const int*)b)[i];
}

// ---------------- setup kernels ----------------
__global__ void k_init() {
    int t = blockIdx.x * blockDim.x + threadIdx.x;
    if (t == 0) g_is64 = 1;
    if (t < B_GRAPHS) g_counts[t] = 0;
}

// batch values < 2^31; if stored int64, every odd 32-bit word in the first N
// words is a (zero) high half. If int32, odd words hold real batch ids that
// become nonzero well before index N. Reads stay within N words => safe both ways.
__global__ void k_detect(const void* batch, int N) {
    const int* w = (const int*)batch;
    int t = blockIdx.x * blockDim.x + threadIdx.x;
    for (int j = 1 + 2 * t; j < N; j += 2 * gridDim.x * blockDim.x) {
        if (w[j] != 0) { g_is64 = 0; return; }
    }
}

__global__ void k_counts(const void* batch, int N) {
    int i = blockIdx.x * blockDim.x + threadIdx.x;
    if (i < N) atomicAdd(&g_counts[get_batch(batch, i)], 1);
}

// exclusive scan of counts over 2048 graphs (1 block, 1024 threads, Hillis-Steele)
__global__ void k_scan() {
    __shared__ int s[B_GRAPHS];
    int t = threadIdx.x;
    int c0 = g_counts[t], c1 = g_counts[t + 1024];
    s[t] = c0; s[t + 1024] = c1;
    __syncthreads();
    for (int d = 1; d < B_GRAPHS; d <<= 1) {
        int a = (t >= d) ? s[t - d] : 0;
        int b = (t + 1024 >= d) ? s[t + 1024 - d] : 0;
        __syncthreads();
        if (t >= d) s[t] += a;
        if (t + 1024 >= d) s[t + 1024] += b;
        __syncthreads();
    }
    g_offsets[t] = s[t] - c0;
    g_offsets[t + 1024] = s[t + 1024] - c1;
}

// for each position p: exclusive prefix over graphs of (count>p), and total
__global__ void k_rowrank() {
    int p = blockIdx.x;
    __shared__ int s[B_GRAPHS];
    int t = threadIdx.x;
    int i0 = (g_counts[t] > p) ? 1 : 0;
    int i1 = (g_counts[t + 1024] > p) ? 1 : 0;
    s[t] = i0; s[t + 1024] = i1;
    __syncthreads();
    for (int d = 1; d < B_GRAPHS; d <<= 1) {
        int a = (t >= d) ? s[t - d] : 0;
        int b = (t + 1024 >= d) ? s[t + 1024 - d] : 0;
        __syncthreads();
        if (t >= d) s[t] += a;
        if (t + 1024 >= d) s[t + 1024] += b;
        __syncthreads();
    }
    g_rowrank[p * B_GRAPHS + t] = s[t] - i0;
    g_rowrank[p * B_GRAPHS + t + 1024] = s[t + 1024] - i1;
    if (t == 0) g_colcnt[p] = s[B_GRAPHS - 1];
}

__global__ void k_colprefix() {
    if (threadIdx.x == 0 && blockIdx.x == 0) {
        int run = 0;
        for (int p = 0; p < LMAX; p++) { g_colprefix[p] = run; run += g_colcnt[p]; }
    }
}

__global__ void k_dest(const void* batch, int N) {
    int i = blockIdx.x * blockDim.x + threadIdx.x;
    if (i < N) {
        int b = get_batch(batch, i);
        int p = i - g_offsets[b];
        g_dest[i] = g_colprefix[p] + g_rowrank[p * B_GRAPHS + b];
    }
}

// W2[i][j] = sum_t w_out[i][t] * out_proj_w[t][j]
__global__ void k_w2(const float* __restrict__ wout, const float* __restrict__ wo) {
    __shared__ float ws[E];
    int i = blockIdx.x, j = threadIdx.x;
    ws[j] = wout[i * E + j];
    __syncthreads();
    float acc = 0.f;
#pragma unroll 8
    for (int t = 0; t < E; t++) acc += ws[t] * wo[t * E + j];
    g_W2[i * E + j] = acc;
}

// b2[j] = sum_t w_out[j][t] * out_proj_b[t] + b_out[j]
__global__ void k_b2(const float* __restrict__ wout, const float* __restrict__ opb,
                     const float* __restrict__ bout) {
    int j = threadIdx.x;
    float acc = bout[j];
    for (int t = 0; t < E; t++) acc += wout[j * E + t] * opb[t];
    g_b2[j] = acc;
}

// ---------------- GEMM1: qkv[N,768] = gather(value)[N,256] @ in_proj_w[768,256]^T + b ----------------
// NT form, both operands K-contiguous. 64x64 tile, BK=16, 256 threads, 4x4 microtile.
__global__ void __launch_bounds__(256) k_gemm1(
    const float* __restrict__ x, const float* __restrict__ metal,
    const float* __restrict__ W, const float* __restrict__ bias,
    const void* __restrict__ batch, int N)
{
    __shared__ float As[16][68];
    __shared__ float Ws[16][68];
    int r0 = blockIdx.x * 64, j0 = blockIdx.y * 64;
    int tid = threadIdx.x;
    int tx = tid & 15, ty = tid >> 4;
    int lr = tid >> 2;            // 0..63 row-in-tile for loading
    int lk = (tid & 3) << 2;      // 0,4,8,12 k-offset

    float acc[4][4];
#pragma unroll
    for (int m = 0; m < 4; m++)
#pragma unroll
        for (int n = 0; n < 4; n++) acc[m][n] = 0.f;

    int arow = r0 + lr;
    int brow = (arow < N) ? get_batch(batch, arow) : 0;
    const float* mrow = metal + (size_t)brow * DM;

    for (int k0 = 0; k0 < E; k0 += 16) {
        float4 av = make_float4(0.f, 0.f, 0.f, 0.f);
        if (arow < N) {
            const float* src = (k0 < DM) ? (mrow + k0 + lk)
                                         : (x + (size_t)arow * DX + (k0 - DM) + lk);
            av = *(const float4*)src;
        }
        As[lk + 0][lr] = av.x; As[lk + 1][lr] = av.y;
        As[lk + 2][lr] = av.z; As[lk + 3][lr] = av.w;

        float4 wv = *(const float4*)(W + (size_t)(j0 + lr) * E + k0 + lk);
        Ws[lk + 0][lr] = wv.x; Ws[lk + 1][lr] = wv.y;
        Ws[lk + 2][lr] = wv.z; Ws[lk + 3][lr] = wv.w;
        __syncthreads();

#pragma unroll
        for (int kk = 0; kk < 16; kk++) {
            float4 a = *(const float4*)&As[kk][ty * 4];
            float4 b = *(const float4*)&Ws[kk][tx * 4];
            acc[0][0] += a.x * b.x; acc[0][1] += a.x * b.y; acc[0][2] += a.x * b.z; acc[0][3] += a.x * b.w;
            acc[1][0] += a.y * b.x; acc[1][1] += a.y * b.y; acc[1][2] += a.y * b.z; acc[1][3] += a.y * b.w;
            acc[2][0] += a.z * b.x; acc[2][1] += a.z * b.y; acc[2][2] += a.z * b.z; acc[2][3] += a.z * b.w;
            acc[3][0] += a.w * b.x; acc[3][1] += a.w * b.y; acc[3][2] += a.w * b.z; acc[3][3] += a.w * b.w;
        }
        __syncthreads();
    }

#pragma unroll
    for (int m = 0; m < 4; m++) {
        int row = r0 + ty * 4 + m;
        if (row < N) {
#pragma unroll
            for (int n = 0; n < 4; n++) {
                int col = j0 + tx * 4 + n;
                g_qkv[(size_t)row * QKV3 + col] = acc[m][n] + bias[col];
            }
        }
    }
}

// ---------------- attention: one block per (graph, head) ----------------
__global__ void __launch_bounds__(256) k_attn() {
    int g = blockIdx.x >> 2;
    int h = blockIdx.x & 3;
    int cnt = g_counts[g];
    int off = g_offsets[g];

    __shared__ float Ks[CMAX * KST];
    __shared__ float Vs[CMAX * KST];
    __shared__ float qs[8 * HD];
    __shared__ float ps[8 * CMAX];

    const float* base = g_qkv + (size_t)off * QKV3;
    for (int idx = threadIdx.x; idx < cnt * HD; idx += blockDim.x) {
        int m = idx >> 6, d = idx & 63;
        Ks[m * KST + d] = base[(size_t)m * QKV3 + E      + h * HD + d];
        Vs[m * KST + d] = base[(size_t)m * QKV3 + 2 * E  + h * HD + d];
    }
    __syncthreads();

    int w = threadIdx.x >> 5, lane = threadIdx.x & 31;
    float* qw = qs + w * HD;
    float* pw = ps + w * CMAX;

    for (int i = w; i < cnt; i += 8) {
        const float* qrow = base + (size_t)i * QKV3 + h * HD;
        qw[lane]      = qrow[lane];
        qw[lane + 32] = qrow[lane + 32];
        __syncwarp();

        float sreg[4];
        float mx = -1e30f;
#pragma unroll
        for (int mi = 0; mi < 4; mi++) {
            int m = lane + mi * 32;
            float s = -1e30f;
            if (m < cnt) {
                s = 0.f;
                const float* kr = Ks + m * KST;
#pragma unroll
                for (int d4 = 0; d4 < 16; d4++) {
                    float4 qv = *(const float4*)&qw[d4 * 4];
                    s += qv.x * kr[d4 * 4 + 0];
                    s += qv.y * kr[d4 * 4 + 1];
                    s += qv.z * kr[d4 * 4 + 2];
                    s += qv.w * kr[d4 * 4 + 3];
                }
                s *= 0.125f;  // 1/sqrt(64)
            }
            sreg[mi] = s;
            mx = fmaxf(mx, s);
        }
#pragma unroll
        for (int o = 16; o; o >>= 1) mx = fmaxf(mx, __shfl_xor_sync(0xFFFFFFFFu, mx, o));

        float sum = 0.f;
#pragma unroll
        for (int mi = 0; mi < 4; mi++) {
            int m = lane + mi * 32;
            float e = (m < cnt) ? __expf(sreg[mi] - mx) : 0.f;
            sreg[mi] = e;
            sum += e;
        }
#pragma unroll
        for (int o = 16; o; o >>= 1) sum += __shfl_xor_sync(0xFFFFFFFFu, sum, o);
        float inv = 1.f / sum;

#pragma unroll
        for (int mi = 0; mi < 4; mi++) {
            int m = lane + mi * 32;
            if (m < cnt) pw[m] = sreg[mi] * inv;
        }
        __syncwarp();

        // P @ V: lane handles d = lane and d = lane+32 (conflict-free LDS,
        // consecutive lanes hit consecutive banks; pw[m] is a broadcast)
        float a0 = 0.f, a1 = 0.f;
        for (int m = 0; m < cnt; m++) {
            float pm = pw[m];
            a0 += pm * Vs[m * KST + lane];
            a1 += pm * Vs[m * KST + lane + 32];
        }
        float* co = g_ctx + (size_t)(off + i) * E + h * HD;
        co[lane]      = a0;
        co[lane + 32] = a1;
        __syncwarp();
    }
}

// ---------------- GEMM2: out[dest[i]] = ctx[i] @ W2^T + b2 ----------------
__global__ void __launch_bounds__(256) k_gemm2(float* __restrict__ out, int N) {
    __shared__ float As[16][68];
    __shared__ float Ws[16][68];
    int r0 = blockIdx.x * 64, j0 = blockIdx.y * 64;
    int tid = threadIdx.x;
    int tx = tid & 15, ty = tid >> 4;
    int lr = tid >> 2;
    int lk = (tid & 3) << 2;

    float acc[4][4];
#pragma unroll
    for (int m = 0; m < 4; m++)
#pragma unroll
        for (int n = 0; n < 4; n++) acc[m][n] = 0.f;

    int arow = r0 + lr;

    for (int k0 = 0; k0 < E; k0 += 16) {
        float4 av = make_float4(0.f, 0.f, 0.f, 0.f);
        if (arow < N) av = *(const float4*)(g_ctx + (size_t)arow * E + k0 + lk);
        As[lk + 0][lr] = av.x; As[lk + 1][lr] = av.y;
        As[lk + 2][lr] = av.z; As[lk + 3][lr] = av.w;

        float4 wv = *(const float4*)(g_W2 + (size_t)(j0 + lr) * E + k0 + lk);
        Ws[lk + 0][lr] = wv.x; Ws[lk + 1][lr] = wv.y;
        Ws[lk + 2][lr] = wv.z; Ws[lk + 3][lr] = wv.w;
        __syncthreads();

#pragma unroll
        for (int kk = 0; kk < 16; kk++) {
            float4 a = *(const float4*)&As[kk][ty * 4];
            float4 b = *(const float4*)&Ws[kk][tx * 4];
            acc[0][0] += a.x * b.x; acc[0][1] += a.x * b.y; acc[0][2] += a.x * b.z; acc[0][3] += a.x * b.w;
            acc[1][0] += a.y * b.x; acc[1][1] += a.y * b.y; acc[1][2] += a.y * b.z; acc[1][3] += a.y * b.w;
            acc[2][0] += a.z * b.x; acc[2][1] += a.z * b.y; acc[2][2] += a.z * b.z; acc[2][3] += a.z * b.w;
            acc[3][0] += a.w * b.x; acc[3][1] += a.w * b.y; acc[3][2] += a.w * b.z; acc[3][3] += a.w * b.w;
        }
        __syncthreads();
    }

#pragma unroll
    for (int m = 0; m < 4; m++) {
        int row = r0 + ty * 4 + m;
        if (row < N) {
            int dr = g_dest[row];
#pragma unroll
            for (int n = 0; n < 4; n++) {
                int col = j0 + tx * 4 + n;
                out[(size_t)dr * E + col] = acc[m][n] + g_b2[col];
            }
        }
    }
}

__global__ void k_copytail(float* __restrict__ dst, const float* __restrict__ metal, int n) {
    int i = blockIdx.x * blockDim.x + threadIdx.x;
    if (i < n && i < B_GRAPHS * DM) dst[i] = metal[i];
}

// ---------------- launch ----------------
extern "C" void kernel_launch(void* const* d_in, const int* in_sizes, int n_in,
                              void* d_out, int out_size) {
    const float* x      = (const float*)d_in[0];
    const float* metal  = (const float*)d_in[1];
    const float* in_w   = (const float*)d_in[2];
    const float* in_b   = (const float*)d_in[3];
    const float* outp_w = (const float*)d_in[4];
    const float* outp_b = (const float*)d_in[5];
    const float* w_out  = (const float*)d_in[6];
    const float* b_out  = (const float*)d_in[7];
    const void*  batch  = d_in[8];
    int N = in_sizes[0] / DX;
    float* out = (float*)d_out;

    k_init<<<(B_GRAPHS + 255) / 256, 256>>>();
    k_detect<<<64, 256>>>(batch, N);
    k_counts<<<(N + 255) / 256, 256>>>(batch, N);
    k_scan<<<1, 1024>>>();
    k_rowrank<<<LMAX, 1024>>>();
    k_colprefix<<<1, 32>>>();
    k_dest<<<(N + 255) / 256, 256>>>(batch, N);
    k_w2<<<E, E>>>(w_out, outp_w);
    k_b2<<<1, E>>>(w_out, outp_b, b_out);

    dim3 g1((N + 63) / 64, QKV3 / 64);
    k_gemm1<<<g1, 256>>>(x, metal, in_w, in_b, batch, N);

    k_attn<<<B_GRAPHS * H, 256>>>();

    dim3 g2((N + 63) / 64, E / 64);
    k_gemm2<<<g2, 256>>>(out, N);

    long long tail = (long long)out_size - (long long)N * E;
    if (tail > 0) {
        k_copytail<<<((int)tail + 255) / 256, 256>>>(out + (size_t)N * E, metal, (int)tail);
    }
}

// round 3
// speedup vs baseline: 1.2951x; 1.2951x over previous
#include <cuda_runtime.h>

// ---------------- problem constants ----------------
#define B_GRAPHS 2048
#define E        256
#define QKV3     768
#define H        4
#define HD       64
#define DM       128
#define DX       128
#define NMAX     (2048*80)
#define LMAX     128
#define CMAX     80
#define KST      65

// ---------------- device scratch ----------------
__device__ int   g_is64;
__device__ int   g_counts[B_GRAPHS];
__device__ int   g_offsets[B_GRAPHS];
__device__ int   g_colcnt[LMAX];
__device__ int   g_colprefix[LMAX];
__device__ int   g_rowrank[LMAX * B_GRAPHS];
__device__ int   g_dest[NMAX];
__device__ float g_qkv[(size_t)NMAX * QKV3];
__device__ float g_ctx[(size_t)NMAX * E];
__device__ float g_W2[E * E];
__device__ float g_b2[E];

__device__ __forceinline__ int get_batch(const void* b, int i) {
    if (g_is64) return (int)((const long long*)b)[i];
    return ((const int*)b)[i];
}

__device__ __forceinline__ unsigned f2tf32(float f) {
    unsigned r;
    asm("cvt.rna.tf32.f32 %0, %1;" : "=r"(r) : "f"(f));
    return r;
}

#define MMA_TF32(d, a, b)                                                     \
  asm volatile("mma.sync.aligned.m16n8k8.row.col.f32.tf32.tf32.f32 "          \
    "{%0,%1,%2,%3}, {%4,%5,%6,%7}, {%8,%9}, {%0,%1,%2,%3};"                   \
    : "+f"((d)[0]), "+f"((d)[1]), "+f"((d)[2]), "+f"((d)[3])                  \
    : "r"((a).x), "r"((a).y), "r"((a).z), "r"((a).w), "r"((b).x), "r"((b).y))

// ---------------- setup kernels ----------------
__global__ void k_init() {
    int t = blockIdx.x * blockDim.x + threadIdx.x;
    if (t == 0) g_is64 = 1;
    if (t < B_GRAPHS) g_counts[t] = 0;
}

__global__ void k_detect(const void* batch, int N) {
    const int* w = (const int*)batch;
    int t = blockIdx.x * blockDim.x + threadIdx.x;
    for (int j = 1 + 2 * t; j < N; j += 2 * gridDim.x * blockDim.x) {
        if (w[j] != 0) { g_is64 = 0; return; }
    }
}

__global__ void k_counts(const void* batch, int N) {
    int i = blockIdx.x * blockDim.x + threadIdx.x;
    if (i < N) atomicAdd(&g_counts[get_batch(batch, i)], 1);
}

__global__ void k_scan() {
    __shared__ int s[B_GRAPHS];
    int t = threadIdx.x;
    int c0 = g_counts[t], c1 = g_counts[t + 1024];
    s[t] = c0; s[t + 1024] = c1;
    __syncthreads();
    for (int d = 1; d < B_GRAPHS; d <<= 1) {
        int a = (t >= d) ? s[t - d] : 0;
        int b = (t + 1024 >= d) ? s[t + 1024 - d] : 0;
        __syncthreads();
        if (t >= d) s[t] += a;
        if (t + 1024 >= d) s[t + 1024] += b;
        __syncthreads();
    }
    g_offsets[t] = s[t] - c0;
    g_offsets[t + 1024] = s[t + 1024] - c1;
}

__global__ void k_rowrank() {
    int p = blockIdx.x;
    __shared__ int s[B_GRAPHS];
    int t = threadIdx.x;
    int i0 = (g_counts[t] > p) ? 1 : 0;
    int i1 = (g_counts[t + 1024] > p) ? 1 : 0;
    s[t] = i0; s[t + 1024] = i1;
    __syncthreads();
    for (int d = 1; d < B_GRAPHS; d <<= 1) {
        int a = (t >= d) ? s[t - d] : 0;
        int b = (t + 1024 >= d) ? s[t + 1024 - d] : 0;
        __syncthreads();
        if (t >= d) s[t] += a;
        if (t + 1024 >= d) s[t + 1024] += b;
        __syncthreads();
    }
    g_rowrank[p * B_GRAPHS + t] = s[t] - i0;
    g_rowrank[p * B_GRAPHS + t + 1024] = s[t + 1024] - i1;
    if (t == 0) g_colcnt[p] = s[B_GRAPHS - 1];
}

__global__ void k_colprefix() {
    if (threadIdx.x == 0 && blockIdx.x == 0) {
        int run = 0;
        for (int p = 0; p < LMAX; p++) { g_colprefix[p] = run; run += g_colcnt[p]; }
    }
}

__global__ void k_dest(const void* batch, int N) {
    int i = blockIdx.x * blockDim.x + threadIdx.x;
    if (i < N) {
        int b = get_batch(batch, i);
        int p = i - g_offsets[b];
        g_dest[i] = g_colprefix[p] + g_rowrank[p * B_GRAPHS + b];
    }
}

__global__ void k_w2(const float* __restrict__ wout, const float* __restrict__ wo) {
    __shared__ float ws[E];
    int i = blockIdx.x, j = threadIdx.x;
    ws[j] = wout[i * E + j];
    __syncthreads();
    float acc = 0.f;
#pragma unroll 8
    for (int t = 0; t < E; t++) acc += ws[t] * wo[t * E + j];
    g_W2[i * E + j] = acc;
}

__global__ void k_b2(const float* __restrict__ wout, const float* __restrict__ opb,
                     const float* __restrict__ bout) {
    int j = threadIdx.x;
    float acc = bout[j];
    for (int t = 0; t < E; t++) acc += wout[j * E + t] * opb[t];
    g_b2[j] = acc;
}

// ---------------- Tensor-core GEMM1 ----------------
// qkv[N,768] = gather(value)[N,256] @ in_proj_w[768,256]^T + bias
// Block: 128(M) x 64(N), BK=32, 8 warps (4x2), warp tile 32x32.
// smem holds tf32 fragments in per-lane order (LDS.128/LDS.64 mainloop loads).
__global__ void __launch_bounds__(256) k_gemm1_tc(
    const float* __restrict__ x, const float* __restrict__ metal,
    const float* __restrict__ W, const float* __restrict__ bias,
    const void* __restrict__ batch, int N)
{
    __shared__ unsigned sA[4096];   // [kt 0..3][mt 0..7][lane][4]
    __shared__ unsigned sB[2048];   // [kt 0..3][nt 0..7][lane][2]
    __shared__ float sbias[64];

    int tid = threadIdx.x;
    int lane = tid & 31, warp = tid >> 5;
    int wm = warp & 3, wn = warp >> 2;
    int r0 = blockIdx.x * 128, j0 = blockIdx.y * 64;

    if (tid < 64) sbias[tid] = bias[j0 + tid];

    // A staging map: row am = tid>>1, ks = (tid&1)*16 + 4j
    int am = tid >> 1;
    int ak0 = (tid & 1) * 16;
    int arow = r0 + am;
    bool avalid = arow < N;
    int ab = avalid ? get_batch(batch, arow) : 0;
    const float* amrow = metal + (size_t)ab * DM;
    const float* axrow = x + (size_t)arow * DX;

    // B staging map: row bn = tid>>2, ks = (tid&3)*8 + 4j
    int bn = tid >> 2;
    int bk0 = (tid & 3) * 8;
    const float* brow = W + (size_t)(j0 + bn) * E;

    float acc[2][4][4];
#pragma unroll
    for (int mi = 0; mi < 2; mi++)
#pragma unroll
        for (int ni = 0; ni < 4; ni++)
#pragma unroll
            for (int c = 0; c < 4; c++) acc[mi][ni][c] = 0.f;

    float4 aval[4], bval[2];
    const float4 z4 = make_float4(0.f, 0.f, 0.f, 0.f);

    // prefetch iter 0
#pragma unroll
    for (int j = 0; j < 4; j++) {
        int kg = ak0 + 4 * j;
        aval[j] = avalid ? *(const float4*)((kg < DM) ? (amrow + kg) : (axrow + kg - DM)) : z4;
    }
#pragma unroll
    for (int j = 0; j < 2; j++) bval[j] = *(const float4*)(brow + bk0 + 4 * j);

    // precomputed staging constants
    int r16 = am & 15, mt = am >> 4;
    int ahi = (r16 >> 3) & 1, ar = r16 & 7;
    int rn = bn & 7, nt = bn >> 3;

    for (int it = 0; it < 8; it++) {
        // stage regs -> smem with cvt + fragment permutation
#pragma unroll
        for (int j = 0; j < 4; j++) {
            int kl = ak0 + 4 * j;
            int kt = kl >> 3, sel = (kl >> 2) & 1;
            unsigned bi = (unsigned)((kt * 8 + mt) * 128 + (ar << 4) + (sel * 2 + ahi));
            sA[bi + 0]  = f2tf32(aval[j].x);
            sA[bi + 4]  = f2tf32(aval[j].y);
            sA[bi + 8]  = f2tf32(aval[j].z);
            sA[bi + 12] = f2tf32(aval[j].w);
        }
#pragma unroll
        for (int j = 0; j < 2; j++) {
            int kl = bk0 + 4 * j;
            int kt = kl >> 3, sel = (kl >> 2) & 1;
            unsigned bi = (unsigned)((kt * 8 + nt) * 64 + (rn << 3) + sel);
            sB[bi + 0] = f2tf32(bval[j].x);
            sB[bi + 2] = f2tf32(bval[j].y);
            sB[bi + 4] = f2tf32(bval[j].z);
            sB[bi + 6] = f2tf32(bval[j].w);
        }
        __syncthreads();

        // prefetch next iter (gmem) while mma runs
        if (it < 7) {
            int knext = (it + 1) * 32;
#pragma unroll
            for (int j = 0; j < 4; j++) {
                int kg = knext + ak0 + 4 * j;
                aval[j] = avalid ? *(const float4*)((kg < DM) ? (amrow + kg) : (axrow + kg - DM)) : z4;
            }
#pragma unroll
            for (int j = 0; j < 2; j++) bval[j] = *(const float4*)(brow + knext + bk0 + 4 * j);
        }

        // mma over the 4 k-subtiles
#pragma unroll
        for (int kt = 0; kt < 4; kt++) {
            uint4 af[2];
            uint2 bf[4];
            af[0] = *(const uint4*)&sA[(kt * 8 + wm * 2 + 0) * 128 + lane * 4];
            af[1] = *(const uint4*)&sA[(kt * 8 + wm * 2 + 1) * 128 + lane * 4];
#pragma unroll
            for (int ni = 0; ni < 4; ni++)
                bf[ni] = *(const uint2*)&sB[(kt * 8 + wn * 4 + ni) * 64 + lane * 2];
#pragma unroll
            for (int mi = 0; mi < 2; mi++)
#pragma unroll
                for (int ni = 0; ni < 4; ni++)
                    MMA_TF32(acc[mi][ni], af[mi], bf[ni]);
        }
        __syncthreads();
    }

    // epilogue: bias + float2 stores
    int mrow0 = r0 + wm * 32;
    int ncol0 = wn * 32;
#pragma unroll
    for (int mi = 0; mi < 2; mi++) {
#pragma unroll
        for (int ni = 0; ni < 4; ni++) {
            float* a4 = acc[mi][ni];
            int row = mrow0 + mi * 16 + (lane >> 2);
            int cl  = ncol0 + ni * 8 + (lane & 3) * 2;
            float b0s = sbias[cl], b1s = sbias[cl + 1];
            if (row < N) {
                float2 v = make_float2(a4[0] + b0s, a4[1] + b1s);
                *(float2*)&g_qkv[(size_t)row * QKV3 + j0 + cl] = v;
            }
            if (row + 8 < N) {
                float2 v = make_float2(a4[2] + b0s, a4[3] + b1s);
                *(float2*)&g_qkv[(size_t)(row + 8) * QKV3 + j0 + cl] = v;
            }
        }
    }
}

// ---------------- Tensor-core GEMM2 ----------------
// out[dest[i]] = ctx[i] @ W2^T + b2    (K = 256, Nout = 256)
__global__ void __launch_bounds__(256) k_gemm2_tc(float* __restrict__ out, int N)
{
    __shared__ unsigned sA[4096];
    __shared__ unsigned sB[2048];
    __shared__ float sbias[64];

    int tid = threadIdx.x;
    int lane = tid & 31, warp = tid >> 5;
    int wm = warp & 3, wn = warp >> 2;
    int r0 = blockIdx.x * 128, j0 = blockIdx.y * 64;

    if (tid < 64) sbias[tid] = g_b2[j0 + tid];

    int am = tid >> 1;
    int ak0 = (tid & 1) * 16;
    int arow = r0 + am;
    bool avalid = arow < N;
    const float* actx = g_ctx + (size_t)arow * E;

    int bn = tid >> 2;
    int bk0 = (tid & 3) * 8;
    const float* brow = g_W2 + (size_t)(j0 + bn) * E;

    float acc[2][4][4];
#pragma unroll
    for (int mi = 0; mi < 2; mi++)
#pragma unroll
        for (int ni = 0; ni < 4; ni++)
#pragma unroll
            for (int c = 0; c < 4; c++) acc[mi][ni][c] = 0.f;

    float4 aval[4], bval[2];
    const float4 z4 = make_float4(0.f, 0.f, 0.f, 0.f);

#pragma unroll
    for (int j = 0; j < 4; j++)
        aval[j] = avalid ? *(const float4*)(actx + ak0 + 4 * j) : z4;
#pragma unroll
    for (int j = 0; j < 2; j++) bval[j] = *(const float4*)(brow + bk0 + 4 * j);

    int r16 = am & 15, mt = am >> 4;
    int ahi = (r16 >> 3) & 1, ar = r16 & 7;
    int rn = bn & 7, nt = bn >> 3;

    for (int it = 0; it < 8; it++) {
#pragma unroll
        for (int j = 0; j < 4; j++) {
            int kl = ak0 + 4 * j;
            int kt = kl >> 3, sel = (kl >> 2) & 1;
            unsigned bi = (unsigned)((kt * 8 + mt) * 128 + (ar << 4) + (sel * 2 + ahi));
            sA[bi + 0]  = f2tf32(aval[j].x);
            sA[bi + 4]  = f2tf32(aval[j].y);
            sA[bi + 8]  = f2tf32(aval[j].z);
            sA[bi + 12] = f2tf32(aval[j].w);
        }
#pragma unroll
        for (int j = 0; j < 2; j++) {
            int kl = bk0 + 4 * j;
            int kt = kl >> 3, sel = (kl >> 2) & 1;
            unsigned bi = (unsigned)((kt * 8 + nt) * 64 + (rn << 3) + sel);
            sB[bi + 0] = f2tf32(bval[j].x);
            sB[bi + 2] = f2tf32(bval[j].y);
            sB[bi + 4] = f2tf32(bval[j].z);
            sB[bi + 6] = f2tf32(bval[j].w);
        }
        __syncthreads();

        if (it < 7) {
            int knext = (it + 1) * 32;
#pragma unroll
            for (int j = 0; j < 4; j++)
                aval[j] = avalid ? *(const float4*)(actx + knext + ak0 + 4 * j) : z4;
#pragma unroll
            for (int j = 0; j < 2; j++) bval[j] = *(const float4*)(brow + knext + bk0 + 4 * j);
        }

#pragma unroll
        for (int kt = 0; kt < 4; kt++) {
            uint4 af[2];
            uint2 bf[4];
            af[0] = *(const uint4*)&sA[(kt * 8 + wm * 2 + 0) * 128 + lane * 4];
            af[1] = *(const uint4*)&sA[(kt * 8 + wm * 2 + 1) * 128 + lane * 4];
#pragma unroll
            for (int ni = 0; ni < 4; ni++)
                bf[ni] = *(const uint2*)&sB[(kt * 8 + wn * 4 + ni) * 64 + lane * 2];
#pragma unroll
            for (int mi = 0; mi < 2; mi++)
#pragma unroll
                for (int ni = 0; ni < 4; ni++)
                    MMA_TF32(acc[mi][ni], af[mi], bf[ni]);
        }
        __syncthreads();
    }

    int mrow0 = r0 + wm * 32;
    int ncol0 = wn * 32;
#pragma unroll
    for (int mi = 0; mi < 2; mi++) {
        int rowA = mrow0 + mi * 16 + (lane >> 2);
        int dA = (rowA < N) ? g_dest[rowA] : 0;
        int dB = (rowA + 8 < N) ? g_dest[rowA + 8] : 0;
#pragma unroll
        for (int ni = 0; ni < 4; ni++) {
            float* a4 = acc[mi][ni];
            int cl = ncol0 + ni * 8 + (lane & 3) * 2;
            float b0s = sbias[cl], b1s = sbias[cl + 1];
            if (rowA < N) {
                float2 v = make_float2(a4[0] + b0s, a4[1] + b1s);
                *(float2*)&out[(size_t)dA * E + j0 + cl] = v;
            }
            if (rowA + 8 < N) {
                float2 v = make_float2(a4[2] + b0s, a4[3] + b1s);
                *(float2*)&out[(size_t)dB * E + j0 + cl] = v;
            }
        }
    }
}

// ---------------- attention: one block per (graph, head) ----------------
__global__ void __launch_bounds__(256) k_attn() {
    int g = blockIdx.x >> 2;
    int h = blockIdx.x & 3;
    int cnt = g_counts[g];
    int off = g_offsets[g];

    __shared__ float Ks[CMAX * KST];
    __shared__ float Vs[CMAX * KST];
    __shared__ float qs[8 * HD];
    __shared__ float ps[8 * CMAX];

    const float* base = g_qkv + (size_t)off * QKV3;
    for (int idx = threadIdx.x; idx < cnt * HD; idx += blockDim.x) {
        int m = idx >> 6, d = idx & 63;
        Ks[m * KST + d] = base[(size_t)m * QKV3 + E      + h * HD + d];
        Vs[m * KST + d] = base[(size_t)m * QKV3 + 2 * E  + h * HD + d];
    }
    __syncthreads();

    int w = threadIdx.x >> 5, lane = threadIdx.x & 31;
    float* qw = qs + w * HD;
    float* pw = ps + w * CMAX;

    for (int i = w; i < cnt; i += 8) {
        const float* qrow = base + (size_t)i * QKV3 + h * HD;
        qw[lane]      = qrow[lane];
        qw[lane + 32] = qrow[lane + 32];
        __syncwarp();

        float sreg[4];
        float mx = -1e30f;
#pragma unroll
        for (int mi = 0; mi < 4; mi++) {
            int m = lane + mi * 32;
            float s = -1e30f;
            if (m < cnt) {
                s = 0.f;
                const float* kr = Ks + m * KST;
#pragma unroll
                for (int d4 = 0; d4 < 16; d4++) {
                    float4 qv = *(const float4*)&qw[d4 * 4];
                    s += qv.x * kr[d4 * 4 + 0];
                    s += qv.y * kr[d4 * 4 + 1];
                    s += qv.z * kr[d4 * 4 + 2];
                    s += qv.w * kr[d4 * 4 + 3];
                }
                s *= 0.125f;
            }
            sreg[mi] = s;
            mx = fmaxf(mx, s);
        }
#pragma unroll
        for (int o = 16; o; o >>= 1) mx = fmaxf(mx, __shfl_xor_sync(0xFFFFFFFFu, mx, o));

        float sum = 0.f;
#pragma unroll
        for (int mi = 0; mi < 4; mi++) {
            int m = lane + mi * 32;
            float e = (m < cnt) ? __expf(sreg[mi] - mx) : 0.f;
            sreg[mi] = e;
            sum += e;
        }
#pragma unroll
        for (int o = 16; o; o >>= 1) sum += __shfl_xor_sync(0xFFFFFFFFu, sum, o);
        float inv = 1.f / sum;

#pragma unroll
        for (int mi = 0; mi < 4; mi++) {
            int m = lane + mi * 32;
            if (m < cnt) pw[m] = sreg[mi] * inv;
        }
        __syncwarp();

        float a0 = 0.f, a1 = 0.f;
        for (int m = 0; m < cnt; m++) {
            float pm = pw[m];
            a0 += pm * Vs[m * KST + lane];
            a1 += pm * Vs[m * KST + lane + 32];
        }
        float* co = g_ctx + (size_t)(off + i) * E + h * HD;
        co[lane]      = a0;
        co[lane + 32] = a1;
        __syncwarp();
    }
}

__global__ void k_copytail(float* __restrict__ dst, const float* __restrict__ metal, int n) {
    int i = blockIdx.x * blockDim.x + threadIdx.x;
    if (i < n && i < B_GRAPHS * DM) dst[i] = metal[i];
}

// ---------------- launch ----------------
extern "C" void kernel_launch(void* const* d_in, const int* in_sizes, int n_in,
                              void* d_out, int out_size) {
    const float* x      = (const float*)d_in[0];
    const float* metal  = (const float*)d_in[1];
    const float* in_w   = (const float*)d_in[2];
    const float* in_b   = (const float*)d_in[3];
    const float* outp_w = (const float*)d_in[4];
    const float* outp_b = (const float*)d_in[5];
    const float* w_out  = (const float*)d_in[6];
    const float* b_out  = (const float*)d_in[7];
    const void*  batch  = d_in[8];
    int N = in_sizes[0] / DX;
    float* out = (float*)d_out;

    k_init<<<(B_GRAPHS + 255) / 256, 256>>>();
    k_detect<<<64, 256>>>(batch, N);
    k_counts<<<(N + 255) / 256, 256>>>(batch, N);
    k_scan<<<1, 1024>>>();
    k_rowrank<<<LMAX, 1024>>>();
    k_colprefix<<<1, 32>>>();
    k_dest<<<(N + 255) / 256, 256>>>(batch, N);
    k_w2<<<E, E>>>(w_out, outp_w);
    k_b2<<<1, E>>>(w_out, outp_b, b_out);

    dim3 g1((N + 127) / 128, QKV3 / 64);
    k_gemm1_tc<<<g1, 256>>>(x, metal, in_w, in_b, batch, N);

    k_attn<<<B_GRAPHS * H, 256>>>();

    dim3 g2((N + 127) / 128, E / 64);
    k_gemm2_tc<<<g2, 256>>>(out, N);

    long long tail = (long long)out_size - (long long)N * E;
    if (tail > 0) {
        k_copytail<<<((int)tail + 255) / 256, 256>>>(out + (size_t)N * E, metal, (int)tail);
    }
}

// round 4
// speedup vs baseline: 2.2912x; 1.7691x over previous
#include <cuda_runtime.h>

// ---------------- problem constants ----------------
#define B_GRAPHS 2048
#define E        256
#define QKV3     768
#define H        4
#define HD       64
#define DM       128
#define DX       128
#define NMAX     (2048*80)
#define LMAX     128
#define CMAX     80
#define KST      65

// GEMM tiling
#define GT_THREADS 512
#define ASTRIDE    260            // 256 + 4 (stride mod 32 == 4 -> conflict-free frag LDS)

// ---------------- device scratch ----------------
__device__ int   g_is64;
__device__ int   g_counts[B_GRAPHS];
__device__ int   g_offsets[B_GRAPHS];
__device__ int   g_colcnt[LMAX];
__device__ int   g_colprefix[LMAX];
__device__ int   g_rowrank[LMAX * B_GRAPHS];
__device__ int   g_dest[NMAX];
__device__ float g_qkv[(size_t)NMAX * QKV3];
__device__ float g_ctx[(size_t)NMAX * E];
__device__ float g_W2[E * E];
__device__ float g_b2[E];
__device__ uint2 g_wf1[96 * 32 * 32];   // in_proj_w tf32 fragments [nt][kt][lane]
__device__ uint2 g_wf2[32 * 32 * 32];   // W2 tf32 fragments

__device__ __forceinline__ int get_batch(const void* b, int i) {
    if (g_is64) return (int)((const long long*)b)[i];
    return ((const int*)b)[i];
}

__device__ __forceinline__ unsigned f2tf32(float f) {
    unsigned r;
    asm("cvt.rna.tf32.f32 %0, %1;" : "=r"(r) : "f"(f));
    return r;
}

#define MMA_TF32(d, a0, a1, a2, a3, b0, b1)                                   \
  asm volatile("mma.sync.aligned.m16n8k8.row.col.f32.tf32.tf32.f32 "          \
    "{%0,%1,%2,%3}, {%4,%5,%6,%7}, {%8,%9}, {%0,%1,%2,%3};"                   \
    : "+f"((d)[0]), "+f"((d)[1]), "+f"((d)[2]), "+f"((d)[3])                  \
    : "r"(a0), "r"(a1), "r"(a2), "r"(a3), "r"(b0), "r"(b1))

#define CP_ASYNC16(dst, src, sz) \
  asm volatile("cp.async.cg.shared.global [%0], [%1], 16, %2;" :: "r"(dst), "l"(src), "r"(sz) : "memory")
#define CP_COMMIT() asm volatile("cp.async.commit_group;" ::: "memory")
#define CP_WAIT1()  asm volatile("cp.async.wait_group 1;" ::: "memory")

// ---------------- setup kernels ----------------
__global__ void k_init() {
    int t = blockIdx.x * blockDim.x + threadIdx.x;
    if (t == 0) g_is64 = 1;
    if (t < B_GRAPHS) g_counts[t] = 0;
}

__global__ void k_detect(const void* batch, int N) {
    const int* w = (const int*)batch;
    int t = blockIdx.x * blockDim.x + threadIdx.x;
    for (int j = 1 + 2 * t; j < N; j += 2 * gridDim.x * blockDim.x) {
        if (w[j] != 0) { g_is64 = 0; return; }
    }
}

__global__ void k_counts(const void* batch, int N) {
    int i = blockIdx.x * blockDim.x + threadIdx.x;
    if (i < N) atomicAdd(&g_counts[get_batch(batch, i)], 1);
}

__global__ void k_scan() {
    __shared__ int s[B_GRAPHS];
    int t = threadIdx.x;
    int c0 = g_counts[t], c1 = g_counts[t + 1024];
    s[t] = c0; s[t + 1024] = c1;
    __syncthreads();
    for (int d = 1; d < B_GRAPHS; d <<= 1) {
        int a = (t >= d) ? s[t - d] : 0;
        int b = (t + 1024 >= d) ? s[t + 1024 - d] : 0;
        __syncthreads();
        if (t >= d) s[t] += a;
        if (t + 1024 >= d) s[t + 1024] += b;
        __syncthreads();
    }
    g_offsets[t] = s[t] - c0;
    g_offsets[t + 1024] = s[t + 1024] - c1;
}

__global__ void k_rowrank() {
    int p = blockIdx.x;
    __shared__ int s[B_GRAPHS];
    int t = threadIdx.x;
    int i0 = (g_counts[t] > p) ? 1 : 0;
    int i1 = (g_counts[t + 1024] > p) ? 1 : 0;
    s[t] = i0; s[t + 1024] = i1;
    __syncthreads();
    for (int d = 1; d < B_GRAPHS; d <<= 1) {
        int a = (t >= d) ? s[t - d] : 0;
        int b = (t + 1024 >= d) ? s[t + 1024 - d] : 0;
        __syncthreads();
        if (t >= d) s[t] += a;
        if (t + 1024 >= d) s[t + 1024] += b;
        __syncthreads();
    }
    g_rowrank[p * B_GRAPHS + t] = s[t] - i0;
    g_rowrank[p * B_GRAPHS + t + 1024] = s[t + 1024] - i1;
    if (t == 0) g_colcnt[p] = s[B_GRAPHS - 1];
}

__global__ void k_colprefix() {
    if (threadIdx.x == 0 && blockIdx.x == 0) {
        int run = 0;
        for (int p = 0; p < LMAX; p++) { g_colprefix[p] = run; run += g_colcnt[p]; }
    }
}

__global__ void k_dest(const void* batch, int N) {
    int i = blockIdx.x * blockDim.x + threadIdx.x;
    if (i < N) {
        int b = get_batch(batch, i);
        int p = i - g_offsets[b];
        g_dest[i] = g_colprefix[p] + g_rowrank[p * B_GRAPHS + b];
    }
}

__global__ void k_w2(const float* __restrict__ wout, const float* __restrict__ wo) {
    __shared__ float ws[E];
    int i = blockIdx.x, j = threadIdx.x;
    ws[j] = wout[i * E + j];
    __syncthreads();
    float acc = 0.f;
#pragma unroll 8
    for (int t = 0; t < E; t++) acc += ws[t] * wo[t * E + j];
    g_W2[i * E + j] = acc;
}

__global__ void k_b2(const float* __restrict__ wout, const float* __restrict__ opb,
                     const float* __restrict__ bout) {
    int j = threadIdx.x;
    float acc = bout[j];
    for (int t = 0; t < E; t++) acc += wout[j * E + t] * opb[t];
    g_b2[j] = acc;
}

// ---------------- weight fragment prep ----------------
// Fragment for mma.m16n8k8 .col B: lane L -> b0=(n=L>>2, k=L&3), b1=(n, k+4).
__global__ void k_wprep1(const float* __restrict__ W) {
    int nt = blockIdx.x;          // 0..95
    int w = threadIdx.x >> 5, lane = threadIdx.x & 31;
    int n = nt * 8 + (lane >> 2);
#pragma unroll
    for (int j = 0; j < 4; j++) {
        int kt = w * 4 + j;
        int k = kt * 8 + (lane & 3);
        uint2 v;
        v.x = f2tf32(W[(size_t)n * E + k]);
        v.y = f2tf32(W[(size_t)n * E + k + 4]);
        g_wf1[(nt * 32 + kt) * 32 + lane] = v;
    }
}

__global__ void k_wprep2() {
    int nt = blockIdx.x;          // 0..31
    int w = threadIdx.x >> 5, lane = threadIdx.x & 31;
    int n = nt * 8 + (lane >> 2);
#pragma unroll
    for (int j = 0; j < 4; j++) {
        int kt = w * 4 + j;
        int k = kt * 8 + (lane & 3);
        uint2 v;
        v.x = f2tf32(g_W2[n * E + k]);
        v.y = f2tf32(g_W2[n * E + k + 4]);
        g_wf2[(nt * 32 + kt) * 32 + lane] = v;
    }
}

// ---------------- unified tensor-core GEMM body ----------------
// A[128 rows x 256 k] resident in smem (row-major, stride ASTRIDE).
// B streamed per (jt,it) from fragment-prepped gmem via cp.async double buffer.
// 16 warps 4(m)x4(n), warp tile 32x32. NJT output column tiles of 128.

struct G1Tag {};  // gemm1: gathered concat A, g_wf1, bias, write qkv
struct G2Tag {};  // gemm2: ctx A, g_wf2, b2, scatter to out via dest

template <int NJT>
__device__ __forceinline__ void gemm_body(
    float* sA, unsigned* sB, int r0, int N,
    const uint2* __restrict__ wf,
    const float* __restrict__ bias,
    float* __restrict__ outp, int out_ld, const int* __restrict__ dest)
{
    const int tid = threadIdx.x;
    const int lane = tid & 31, warp = tid >> 5;
    const int wm = warp & 3, wn = warp >> 2;
    const int NP = NJT * 8;

    // ---- issue B(p=0) ----
    {
#pragma unroll
        for (int j = 0; j < 2; j++) {
            int c = tid + GT_THREADS * j;            // 0..1023
            int cc = c & 15, nt_loc = (c >> 4) & 15, kt_loc = c >> 8;
            const uint2* src = wf + (size_t)((0 + nt_loc) * 32 + 0 + kt_loc) * 32 + cc * 2;
            unsigned dst = (unsigned)__cvta_generic_to_shared(sB) + (unsigned)c * 16;
            CP_ASYNC16(dst, src, 16);
        }
    }
    CP_COMMIT();

    int p = 0;
    for (int jt = 0; jt < NJT; jt++) {
        float acc[2][4][4];
#pragma unroll
        for (int mi = 0; mi < 2; mi++)
#pragma unroll
            for (int ni = 0; ni < 4; ni++)
#pragma unroll
                for (int c = 0; c < 4; c++) acc[mi][ni][c] = 0.f;

        for (int it = 0; it < 8; it++, p++) {
            // prefetch B(p+1)
            if (p + 1 < NP) {
                int pn = p + 1;
                int ntb = (pn >> 3) * 16, ktb = (pn & 7) * 4;
                unsigned* sBn = sB + ((pn & 1) ? 4096 : 0);
#pragma unroll
                for (int j = 0; j < 2; j++) {
                    int c = tid + GT_THREADS * j;
                    int cc = c & 15, nt_loc = (c >> 4) & 15, kt_loc = c >> 8;
                    const uint2* src = wf + (size_t)((ntb + nt_loc) * 32 + ktb + kt_loc) * 32 + cc * 2;
                    unsigned dst = (unsigned)__cvta_generic_to_shared(sBn) + (unsigned)c * 16;
                    CP_ASYNC16(dst, src, 16);
                }
            }
            CP_COMMIT();
            CP_WAIT1();
            __syncthreads();

            const unsigned* sBc = sB + ((p & 1) ? 4096 : 0);
            const float* apbase0 = sA + (wm * 32 + (lane >> 2)) * ASTRIDE + it * 32 + (lane & 3);
#pragma unroll
            for (int kt = 0; kt < 4; kt++) {
                // B fragments
                uint2 bf[4];
#pragma unroll
                for (int ni = 0; ni < 4; ni++)
                    bf[ni] = *(const uint2*)&sBc[((kt * 16 + wn * 4 + ni) << 6) + lane * 2];
                // A fragments + mma
#pragma unroll
                for (int mi = 0; mi < 2; mi++) {
                    const float* ap = apbase0 + mi * 16 * ASTRIDE + kt * 8;
                    unsigned a0 = f2tf32(ap[0]);
                    unsigned a1 = f2tf32(ap[8 * ASTRIDE]);
                    unsigned a2 = f2tf32(ap[4]);
                    unsigned a3 = f2tf32(ap[8 * ASTRIDE + 4]);
#pragma unroll
                    for (int ni = 0; ni < 4; ni++)
                        MMA_TF32(acc[mi][ni], a0, a1, a2, a3, bf[ni].x, bf[ni].y);
                }
            }
            __syncthreads();
        }

        // epilogue for jt
        int j0 = jt * 128;
#pragma unroll
        for (int mi = 0; mi < 2; mi++) {
            int row = r0 + wm * 32 + mi * 16 + (lane >> 2);
            int rowB = row + 8;
            int drA = 0, drB = 0;
            bool vA = row < N, vB = rowB < N;
            if (dest) {
                drA = vA ? dest[row] : 0;
                drB = vB ? dest[rowB] : 0;
            } else { drA = row; drB = rowB; }
#pragma unroll
            for (int ni = 0; ni < 4; ni++) {
                int col = j0 + wn * 32 + ni * 8 + (lane & 3) * 2;
                float b0 = bias[col], b1 = bias[col + 1];
                float* a4 = acc[mi][ni];
                if (vA) {
                    float2 v = make_float2(a4[0] + b0, a4[1] + b1);
                    *(float2*)&outp[(size_t)drA * out_ld + col] = v;
                }
                if (vB) {
                    float2 v = make_float2(a4[2] + b0, a4[3] + b1);
                    *(float2*)&outp[(size_t)drB * out_ld + col] = v;
                }
            }
        }
    }
}

// GEMM1: qkv = gather(concat(metal[batch], x)) @ in_proj_w^T + bias
__global__ void __launch_bounds__(GT_THREADS, 1) k_gemm1_tc(
    const float* __restrict__ x, const float* __restrict__ metal,
    const float* __restrict__ bias, const void* __restrict__ batch, int N)
{
    extern __shared__ char smem[];
    float* sA = (float*)smem;                              // 128*260 floats
    unsigned* sB = (unsigned*)(smem + 128 * ASTRIDE * 4);  // 2*4096 uints
    int* srcm = (int*)(smem + 128 * ASTRIDE * 4 + 2 * 4096 * 4);

    int tid = threadIdx.x;
    int r0 = blockIdx.x * 128;

    if (tid < 128) {
        int ar = r0 + tid;
        srcm[tid] = (ar < N) ? get_batch(batch, ar) : 0;
    }
    __syncthreads();

    // load A (concat gather) via cp.async, zfill for invalid rows
    unsigned sAaddr = (unsigned)__cvta_generic_to_shared(sA);
#pragma unroll
    for (int r = 0; r < 16; r++) {
        int f = tid + GT_THREADS * r;      // 0..8191
        int row = f >> 6, c4 = f & 63;
        int arow = r0 + row;
        bool valid = arow < N;
        const float* src = (c4 < 32)
            ? metal + (size_t)srcm[row] * DM + c4 * 4
            : x + (size_t)arow * DX + (c4 - 32) * 4;
        if (!valid) src = metal;
        CP_ASYNC16(sAaddr + (unsigned)(row * ASTRIDE + c4 * 4) * 4, src, valid ? 16 : 0);
    }

    gemm_body<6>(sA, sB, r0, N, g_wf1, bias, g_qkv, QKV3, nullptr);
}

// GEMM2: out[dest[i]] = ctx[i] @ W2^T + b2
__global__ void __launch_bounds__(GT_THREADS, 1) k_gemm2_tc(float* __restrict__ out, int N)
{
    extern __shared__ char smem[];
    float* sA = (float*)smem;
    unsigned* sB = (unsigned*)(smem + 128 * ASTRIDE * 4);

    int tid = threadIdx.x;
    int r0 = blockIdx.x * 128;

    unsigned sAaddr = (unsigned)__cvta_generic_to_shared(sA);
#pragma unroll
    for (int r = 0; r < 16; r++) {
        int f = tid + GT_THREADS * r;
        int row = f >> 6, c4 = f & 63;
        int arow = r0 + row;
        bool valid = arow < N;
        const float* src = g_ctx + (size_t)(valid ? arow : 0) * E + c4 * 4;
        CP_ASYNC16(sAaddr + (unsigned)(row * ASTRIDE + c4 * 4) * 4, src, valid ? 16 : 0);
    }

    gemm_body<2>(sA, sB, r0, N, g_wf2, g_b2, out, E, g_dest);
}

// ---------------- attention: one block per (graph, head), 4 queries per warp ----------------
__global__ void __launch_bounds__(256) k_attn() {
    extern __shared__ float sm[];
    float* Ks = sm;                    // 80*65
    float* Vs = Ks + CMAX * KST;       // 80*65
    float* qs = Vs + CMAX * KST;       // 8*4*64
    float* ps = qs + 8 * 4 * HD;       // 8*4*80

    int g = blockIdx.x >> 2;
    int h = blockIdx.x & 3;
    int cnt = g_counts[g];
    int off = g_offsets[g];

    const float* base = g_qkv + (size_t)off * QKV3;
    for (int idx = threadIdx.x; idx < cnt * HD; idx += blockDim.x) {
        int m = idx >> 6, d = idx & 63;
        Ks[m * KST + d] = base[(size_t)m * QKV3 + E     + h * HD + d];
        Vs[m * KST + d] = base[(size_t)m * QKV3 + 2 * E + h * HD + d];
    }
    __syncthreads();

    int w = threadIdx.x >> 5, lane = threadIdx.x & 31;
    float* qw = qs + w * 4 * HD;
    float* pw = ps + w * 4 * CMAX;

    for (int q0 = w * 4; q0 < cnt; q0 += 32) {
        // load up to 4 query vectors
#pragma unroll
        for (int qi = 0; qi < 4; qi++) {
            int qidx = q0 + qi;
            const float* qrow = base + (size_t)((qidx < cnt) ? qidx : q0) * QKV3 + h * HD;
            qw[qi * HD + lane]      = qrow[lane];
            qw[qi * HD + lane + 32] = qrow[lane + 32];
        }
        __syncwarp();

        float s[3][4];
        float mx[4] = {-1e30f, -1e30f, -1e30f, -1e30f};
#pragma unroll
        for (int mi = 0; mi < 3; mi++) {
            int m = lane + mi * 32;
            bool act = m < cnt;
            float a0 = 0.f, a1 = 0.f, a2 = 0.f, a3 = 0.f;
            const float* kr = Ks + m * KST;
            if (act) {
#pragma unroll
                for (int d4 = 0; d4 < 16; d4++) {
                    float k0 = kr[d4 * 4 + 0], k1 = kr[d4 * 4 + 1];
                    float k2 = kr[d4 * 4 + 2], k3 = kr[d4 * 4 + 3];
                    float4 v0 = *(const float4*)&qw[0 * HD + d4 * 4];
                    float4 v1 = *(const float4*)&qw[1 * HD + d4 * 4];
                    float4 v2 = *(const float4*)&qw[2 * HD + d4 * 4];
                    float4 v3 = *(const float4*)&qw[3 * HD + d4 * 4];
                    a0 += v0.x * k0 + v0.y * k1 + v0.z * k2 + v0.w * k3;
                    a1 += v1.x * k0 + v1.y * k1 + v1.z * k2 + v1.w * k3;
                    a2 += v2.x * k0 + v2.y * k1 + v2.z * k2 + v2.w * k3;
                    a3 += v3.x * k0 + v3.y * k1 + v3.z * k2 + v3.w * k3;
                }
            }
            s[mi][0] = act ? a0 * 0.125f : -1e30f;
            s[mi][1] = act ? a1 * 0.125f : -1e30f;
            s[mi][2] = act ? a2 * 0.125f : -1e30f;
            s[mi][3] = act ? a3 * 0.125f : -1e30f;
#pragma unroll
            for (int qi = 0; qi < 4; qi++) mx[qi] = fmaxf(mx[qi], s[mi][qi]);
        }
#pragma unroll
        for (int qi = 0; qi < 4; qi++)
#pragma unroll
            for (int o = 16; o; o >>= 1)
                mx[qi] = fmaxf(mx[qi], __shfl_xor_sync(0xFFFFFFFFu, mx[qi], o));

        float sum[4] = {0.f, 0.f, 0.f, 0.f};
#pragma unroll
        for (int mi = 0; mi < 3; mi++) {
            int m = lane + mi * 32;
            bool act = m < cnt;
#pragma unroll
            for (int qi = 0; qi < 4; qi++) {
                float e = act ? __expf(s[mi][qi] - mx[qi]) : 0.f;
                s[mi][qi] = e;
                sum[qi] += e;
            }
        }
#pragma unroll
        for (int qi = 0; qi < 4; qi++)
#pragma unroll
            for (int o = 16; o; o >>= 1)
                sum[qi] += __shfl_xor_sync(0xFFFFFFFFu, sum[qi], o);

        float inv[4];
#pragma unroll
        for (int qi = 0; qi < 4; qi++) inv[qi] = 1.f / sum[qi];

#pragma unroll
        for (int mi = 0; mi < 3; mi++) {
            int m = lane + mi * 32;
            if (m < cnt) {
#pragma unroll
                for (int qi = 0; qi < 4; qi++) pw[qi * CMAX + m] = s[mi][qi] * inv[qi];
            }
        }
        __syncwarp();

        float a[4][2];
#pragma unroll
        for (int qi = 0; qi < 4; qi++) { a[qi][0] = 0.f; a[qi][1] = 0.f; }
        for (int m = 0; m < cnt; m++) {
            float v0 = Vs[m * KST + lane];
            float v1 = Vs[m * KST + lane + 32];
#pragma unroll
            for (int qi = 0; qi < 4; qi++) {
                float pm = pw[qi * CMAX + m];
                a[qi][0] += pm * v0;
                a[qi][1] += pm * v1;
            }
        }
#pragma unroll
        for (int qi = 0; qi < 4; qi++) {
            int qidx = q0 + qi;
            if (qidx < cnt) {
                float* co = g_ctx + (size_t)(off + qidx) * E + h * HD;
                co[lane]      = a[qi][0];
                co[lane + 32] = a[qi][1];
            }
        }
        __syncwarp();
    }
}

__global__ void k_copytail(float* __restrict__ dst, const float* __restrict__ metal, int n) {
    int i = blockIdx.x * blockDim.x + threadIdx.x;
    if (i < n && i < B_GRAPHS * DM) dst[i] = metal[i];
}

// ---------------- launch ----------------
extern "C" void kernel_launch(void* const* d_in, const int* in_sizes, int n_in,
                              void* d_out, int out_size) {
    const float* x      = (const float*)d_in[0];
    const float* metal  = (const float*)d_in[1];
    const float* in_w   = (const float*)d_in[2];
    const float* in_b   = (const float*)d_in[3];
    const float* outp_w = (const float*)d_in[4];
    const float* outp_b = (const float*)d_in[5];
    const float* w_out  = (const float*)d_in[6];
    const float* b_out  = (const float*)d_in[7];
    const void*  batch  = d_in[8];
    int N = in_sizes[0] / DX;
    float* out = (float*)d_out;

    const int SMEM_G1  = 128 * ASTRIDE * 4 + 2 * 4096 * 4 + 512;
    const int SMEM_G2  = 128 * ASTRIDE * 4 + 2 * 4096 * 4;
    const int SMEM_ATT = (2 * CMAX * KST + 8 * 4 * HD + 8 * 4 * CMAX) * 4;

    cudaFuncSetAttribute(k_gemm1_tc, cudaFuncAttributeMaxDynamicSharedMemorySize, SMEM_G1);
    cudaFuncSetAttribute(k_gemm2_tc, cudaFuncAttributeMaxDynamicSharedMemorySize, SMEM_G2);
    cudaFuncSetAttribute(k_attn,     cudaFuncAttributeMaxDynamicSharedMemorySize, SMEM_ATT);

    k_init<<<(B_GRAPHS + 255) / 256, 256>>>();
    k_detect<<<64, 256>>>(batch, N);
    k_wprep1<<<96, 256>>>(in_w);

    int nblk = (N + 127) / 128;
    k_gemm1_tc<<<nblk, GT_THREADS, SMEM_G1>>>(x, metal, in_b, batch, N);

    k_counts<<<(N + 255) / 256, 256>>>(batch, N);
    k_scan<<<1, 1024>>>();
    k_rowrank<<<LMAX, 1024>>>();
    k_colprefix<<<1, 32>>>();
    k_dest<<<(N + 255) / 256, 256>>>(batch, N);
    k_w2<<<E, E>>>(w_out, outp_w);
    k_b2<<<1, E>>>(w_out, outp_b, b_out);
    k_wprep2<<<32, 256>>>();

    k_attn<<<B_GRAPHS * H, 256, SMEM_ATT>>>();

    k_gemm2_tc<<<nblk, GT_THREADS, SMEM_G2>>>(out, N);

    long long tail = (long long)out_size - (long long)N * E;
    if (tail > 0) {
        k_copytail<<<((int)tail + 255) / 256, 256>>>(out + (size_t)N * E, metal, (int)tail);
    }
}

// round 5
// speedup vs baseline: 2.2950x; 1.0017x over previous
#include <cuda_runtime.h>

// ---------------- problem constants ----------------
#define B_GRAPHS 2048
#define E        256
#define QKV3     768
#define H        4
#define HD       64
#define DM       128
#define DX       128
#define NMAX     (2048*80)
#define LMAX     128
#define CMAX     80
#define KST      65

#define GT_THREADS 256

// ---------------- device scratch ----------------
__device__ int   g_is64;
__device__ int   g_counts[B_GRAPHS];
__device__ int   g_offsets[B_GRAPHS];
__device__ int   g_colcnt[LMAX];
__device__ int   g_colprefix[LMAX];
__device__ int   g_rowrank[LMAX * B_GRAPHS];
__device__ int   g_dest[NMAX];
__device__ float g_qkv[(size_t)NMAX * QKV3];
__device__ float g_ctx[(size_t)NMAX * E];
__device__ float g_W2[E * E];
__device__ float g_b2[E];
__device__ uint2 g_wf1[96 * 32 * 32];   // in_proj_w tf32 fragments [nt][kt][lane]
__device__ uint2 g_wf2[32 * 32 * 32];   // W2 tf32 fragments

__device__ __forceinline__ int get_batch(const void* b, int i) {
    if (g_is64) return (int)((const long long*)b)[i];
    return ((const int*)b)[i];
}

__device__ __forceinline__ unsigned f2tf32(float f) {
    unsigned r;
    asm("cvt.rna.tf32.f32 %0, %1;" : "=r"(r) : "f"(f));
    return r;
}

#define MMA_TF32(d, a0, a1, a2, a3, b0, b1)                                   \
  asm volatile("mma.sync.aligned.m16n8k8.row.col.f32.tf32.tf32.f32 "          \
    "{%0,%1,%2,%3}, {%4,%5,%6,%7}, {%8,%9}, {%0,%1,%2,%3};"                   \
    : "+f"((d)[0]), "+f"((d)[1]), "+f"((d)[2]), "+f"((d)[3])                  \
    : "r"(a0), "r"(a1), "r"(a2), "r"(a3), "r"(b0), "r"(b1))

#define CP_ASYNC16(dst, src) \
  asm volatile("cp.async.cg.shared.global [%0], [%1], 16;" :: "r"(dst), "l"(src) : "memory")
#define CP_COMMIT() asm volatile("cp.async.commit_group;" ::: "memory")
#define CP_WAIT2()  asm volatile("cp.async.wait_group 2;" ::: "memory")

// ---------------- setup kernels ----------------
__global__ void k_init() {
    int t = blockIdx.x * blockDim.x + threadIdx.x;
    if (t == 0) g_is64 = 1;
    if (t < B_GRAPHS) g_counts[t] = 0;
}

__global__ void k_detect(const void* batch, int N) {
    const int* w = (const int*)batch;
    int t = blockIdx.x * blockDim.x + threadIdx.x;
    for (int j = 1 + 2 * t; j < N; j += 2 * gridDim.x * blockDim.x) {
        if (w[j] != 0) { g_is64 = 0; return; }
    }
}

__global__ void k_counts(const void* batch, int N) {
    int i = blockIdx.x * blockDim.x + threadIdx.x;
    if (i < N) atomicAdd(&g_counts[get_batch(batch, i)], 1);
}

__global__ void k_scan() {
    __shared__ int s[B_GRAPHS];
    int t = threadIdx.x;
    int c0 = g_counts[t], c1 = g_counts[t + 1024];
    s[t] = c0; s[t + 1024] = c1;
    __syncthreads();
    for (int d = 1; d < B_GRAPHS; d <<= 1) {
        int a = (t >= d) ? s[t - d] : 0;
        int b = (t + 1024 >= d) ? s[t + 1024 - d] : 0;
        __syncthreads();
        if (t >= d) s[t] += a;
        if (t + 1024 >= d) s[t + 1024] += b;
        __syncthreads();
    }
    g_offsets[t] = s[t] - c0;
    g_offsets[t + 1024] = s[t + 1024] - c1;
}

__global__ void k_rowrank() {
    int p = blockIdx.x;
    __shared__ int s[B_GRAPHS];
    int t = threadIdx.x;
    int i0 = (g_counts[t] > p) ? 1 : 0;
    int i1 = (g_counts[t + 1024] > p) ? 1 : 0;
    s[t] = i0; s[t + 1024] = i1;
    __syncthreads();
    for (int d = 1; d < B_GRAPHS; d <<= 1) {
        int a = (t >= d) ? s[t - d] : 0;
        int b = (t + 1024 >= d) ? s[t + 1024 - d] : 0;
        __syncthreads();
        if (t >= d) s[t] += a;
        if (t + 1024 >= d) s[t + 1024] += b;
        __syncthreads();
    }
    g_rowrank[p * B_GRAPHS + t] = s[t] - i0;
    g_rowrank[p * B_GRAPHS + t + 1024] = s[t + 1024] - i1;
    if (t == 0) g_colcnt[p] = s[B_GRAPHS - 1];
}

__global__ void k_colprefix() {
    if (threadIdx.x == 0 && blockIdx.x == 0) {
        int run = 0;
        for (int p = 0; p < LMAX; p++) { g_colprefix[p] = run; run += g_colcnt[p]; }
    }
}

__global__ void k_dest(const void* batch, int N) {
    int i = blockIdx.x * blockDim.x + threadIdx.x;
    if (i < N) {
        int b = get_batch(batch, i);
        int p = i - g_offsets[b];
        g_dest[i] = g_colprefix[p] + g_rowrank[p * B_GRAPHS + b];
    }
}

__global__ void k_w2(const float* __restrict__ wout, const float* __restrict__ wo) {
    __shared__ float ws[E];
    int i = blockIdx.x, j = threadIdx.x;
    ws[j] = wout[i * E + j];
    __syncthreads();
    float acc = 0.f;
#pragma unroll 8
    for (int t = 0; t < E; t++) acc += ws[t] * wo[t * E + j];
    g_W2[i * E + j] = acc;
}

__global__ void k_b2(const float* __restrict__ wout, const float* __restrict__ opb,
                     const float* __restrict__ bout) {
    int j = threadIdx.x;
    float acc = bout[j];
    for (int t = 0; t < E; t++) acc += wout[j * E + t] * opb[t];
    g_b2[j] = acc;
}

// ---------------- weight fragment prep ----------------
__global__ void k_wprep1(const float* __restrict__ W) {
    int nt = blockIdx.x;          // 0..95
    int w = threadIdx.x >> 5, lane = threadIdx.x & 31;
    int n = nt * 8 + (lane >> 2);
#pragma unroll
    for (int j = 0; j < 4; j++) {
        int kt = w * 4 + j;
        int k = kt * 8 + (lane & 3);
        uint2 v;
        v.x = f2tf32(W[(size_t)n * E + k]);
        v.y = f2tf32(W[(size_t)n * E + k + 4]);
        g_wf1[(nt * 32 + kt) * 32 + lane] = v;
    }
}

__global__ void k_wprep2() {
    int nt = blockIdx.x;          // 0..31
    int w = threadIdx.x >> 5, lane = threadIdx.x & 31;
    int n = nt * 8 + (lane >> 2);
#pragma unroll
    for (int j = 0; j < 4; j++) {
        int kt = w * 4 + j;
        int k = kt * 8 + (lane & 3);
        uint2 v;
        v.x = f2tf32(g_W2[n * E + k]);
        v.y = f2tf32(g_W2[n * E + k + 4]);
        g_wf2[(nt * 32 + kt) * 32 + lane] = v;
    }
}

// ---------------- GEMM core ----------------
// A resident in smem as tf32 fragments: sAf[ktg 0..31][mt 0..7][lane][4] (128KB).
// B streamed from fragment-prepped gmem via 4-stage cp.async ring.
// 8 warps: 2(m) x 4(n), warp tile 64x32 (mi=4, ni=4).

__device__ __forceinline__ void issue_B_stage(unsigned* sB, const uint2* __restrict__ wf,
                                              int ps, int tid) {
    int ntb = (ps >> 3) * 16, ktb = (ps & 7) * 4;
    unsigned base = (unsigned)__cvta_generic_to_shared(sB + (ps & 3) * 4096);
#pragma unroll
    for (int j = 0; j < 4; j++) {
        int c = tid + GT_THREADS * j;    // 0..1023
        int cc = c & 15, nt_loc = (c >> 4) & 15, kt_loc = c >> 8;
        const uint2* src = wf + (size_t)((ntb + nt_loc) * 32 + ktb + kt_loc) * 32 + cc * 2;
        CP_ASYNC16(base + (unsigned)c * 16, src);
    }
}

template <int NJT>
__device__ __forceinline__ void gemm_body(
    const unsigned* sAf, unsigned* sB, int r0, int N,
    const uint2* __restrict__ wf,
    const float* __restrict__ bias,
    float* __restrict__ outp, int out_ld, const int* __restrict__ dest)
{
    const int tid = threadIdx.x;
    const int lane = tid & 31, warp = tid >> 5;
    const int wm = warp >> 2, wn = warp & 3;
    const int NP = NJT * 8;

    // prologue: stages 0..2
    issue_B_stage(sB, wf, 0, tid); CP_COMMIT();
    issue_B_stage(sB, wf, 1, tid); CP_COMMIT();
    issue_B_stage(sB, wf, 2, tid); CP_COMMIT();

    int p = 0;
    for (int jt = 0; jt < NJT; jt++) {
        float acc[4][4][4];
#pragma unroll
        for (int mi = 0; mi < 4; mi++)
#pragma unroll
            for (int ni = 0; ni < 4; ni++)
#pragma unroll
                for (int c = 0; c < 4; c++) acc[mi][ni][c] = 0.f;

        for (int it = 0; it < 8; it++, p++) {
            CP_WAIT2();
            __syncthreads();
            if (p + 3 < NP) issue_B_stage(sB, wf, p + 3, tid);
            CP_COMMIT();

            const unsigned* sBc = sB + (p & 3) * 4096;
#pragma unroll
            for (int kt = 0; kt < 4; kt++) {
                int ktg = it * 4 + kt;
                uint2 bf[4];
#pragma unroll
                for (int ni = 0; ni < 4; ni++)
                    bf[ni] = *(const uint2*)&sBc[((kt * 16 + wn * 4 + ni) << 6) + lane * 2];
                uint4 af[4];
#pragma unroll
                for (int mi = 0; mi < 4; mi++)
                    af[mi] = *(const uint4*)&sAf[((ktg * 8 + wm * 4 + mi) * 32 + lane) * 4];
#pragma unroll
                for (int mi = 0; mi < 4; mi++)
#pragma unroll
                    for (int ni = 0; ni < 4; ni++)
                        MMA_TF32(acc[mi][ni], af[mi].x, af[mi].y, af[mi].z, af[mi].w,
                                 bf[ni].x, bf[ni].y);
            }
        }

        // epilogue (registers + gmem only; safe to overlap with next jt's barrier)
        int j0 = jt * 128;
#pragma unroll
        for (int mi = 0; mi < 4; mi++) {
            int rowA = r0 + wm * 64 + mi * 16 + (lane >> 2);
            int rowB = rowA + 8;
            bool vA = rowA < N, vB = rowB < N;
            int drA, drB;
            if (dest) { drA = vA ? dest[rowA] : 0; drB = vB ? dest[rowB] : 0; }
            else      { drA = rowA; drB = rowB; }
#pragma unroll
            for (int ni = 0; ni < 4; ni++) {
                int col = j0 + wn * 32 + ni * 8 + (lane & 3) * 2;
                float b0 = bias[col], b1 = bias[col + 1];
                float* a4 = acc[mi][ni];
                if (vA) {
                    float2 v = make_float2(a4[0] + b0, a4[1] + b1);
                    *(float2*)&outp[(size_t)drA * out_ld + col] = v;
                }
                if (vB) {
                    float2 v = make_float2(a4[2] + b0, a4[3] + b1);
                    *(float2*)&outp[(size_t)drB * out_ld + col] = v;
                }
            }
        }
    }
}

// GEMM1: qkv = gather(concat(metal[batch], x)) @ in_proj_w^T + bias
__global__ void __launch_bounds__(GT_THREADS, 1) k_gemm1_tc(
    const float* __restrict__ x, const float* __restrict__ metal,
    const float* __restrict__ bias, const void* __restrict__ batch, int N)
{
    extern __shared__ char smem[];
    unsigned* sAf = (unsigned*)smem;                 // 32768 uints = 128KB
    unsigned* sB  = sAf + 32768;                     // 4*4096 uints = 64KB
    int* srcm     = (int*)(sB + 4 * 4096);           // 128 ints

    int tid = threadIdx.x;
    int r0 = blockIdx.x * 128;

    if (tid < 128) {
        int ar = r0 + tid;
        srcm[tid] = (ar < N) ? get_batch(batch, ar) : 0;
    }
    __syncthreads();

    // stage A into fragment order (thread owns one fragment-lane; STS.128 conflict-free)
    {
        int mt = (tid >> 5) & 7, le = tid & 31;
        int r8 = le >> 2, kk = le & 3;
        int rowA = mt * 16 + r8, rowB = rowA + 8;
        int gA = r0 + rowA, gB = r0 + rowB;
        bool vA = gA < N, vB = gB < N;
        const float* mA = metal + (size_t)srcm[rowA] * DM;
        const float* mB = metal + (size_t)srcm[rowB] * DM;
        const float* xA = x + (size_t)gA * DX;
        const float* xB = x + (size_t)gB * DX;
#pragma unroll 4
        for (int q = 0; q < 32; q++) {
            int k = q * 8 + kk;
            float v0, v1, v2, v3;
            if (q < 16) {   // k, k+4 both < 128 -> metal half
                v0 = vA ? mA[k] : 0.f;
                v1 = vB ? mB[k] : 0.f;
                v2 = vA ? mA[k + 4] : 0.f;
                v3 = vB ? mB[k + 4] : 0.f;
            } else {        // x half
                v0 = vA ? xA[k - 128] : 0.f;
                v1 = vB ? xB[k - 128] : 0.f;
                v2 = vA ? xA[k - 124] : 0.f;
                v3 = vB ? xB[k - 124] : 0.f;
            }
            uint4 u;
            u.x = f2tf32(v0); u.y = f2tf32(v1); u.z = f2tf32(v2); u.w = f2tf32(v3);
            *(uint4*)&sAf[(size_t)((q * 8 + mt) * 32 + le) * 4] = u;
        }
    }
    // note: first mainloop barrier (after CP_WAIT2) also fences A staging

    gemm_body<6>(sAf, sB, r0, N, g_wf1, bias, g_qkv, QKV3, nullptr);
}

// GEMM2: out[dest[i]] = ctx[i] @ W2^T + b2
__global__ void __launch_bounds__(GT_THREADS, 1) k_gemm2_tc(float* __restrict__ out, int N)
{
    extern __shared__ char smem[];
    unsigned* sAf = (unsigned*)smem;
    unsigned* sB  = sAf + 32768;

    int tid = threadIdx.x;
    int r0 = blockIdx.x * 128;

    {
        int mt = (tid >> 5) & 7, le = tid & 31;
        int r8 = le >> 2, kk = le & 3;
        int rowA = mt * 16 + r8, rowB = rowA + 8;
        int gA = r0 + rowA, gB = r0 + rowB;
        bool vA = gA < N, vB = gB < N;
        const float* cA = g_ctx + (size_t)gA * E;
        const float* cB = g_ctx + (size_t)gB * E;
#pragma unroll 4
        for (int q = 0; q < 32; q++) {
            int k = q * 8 + kk;
            float v0 = vA ? cA[k] : 0.f;
            float v1 = vB ? cB[k] : 0.f;
            float v2 = vA ? cA[k + 4] : 0.f;
            float v3 = vB ? cB[k + 4] : 0.f;
            uint4 u;
            u.x = f2tf32(v0); u.y = f2tf32(v1); u.z = f2tf32(v2); u.w = f2tf32(v3);
            *(uint4*)&sAf[(size_t)((q * 8 + mt) * 32 + le) * 4] = u;
        }
    }

    gemm_body<2>(sAf, sB, r0, N, g_wf2, g_b2, out, E, g_dest);
}

// ---------------- attention: one block per (graph, head), 4 queries per warp ----------------
__global__ void __launch_bounds__(256) k_attn() {
    extern __shared__ float sm[];
    float* Ks = sm;                    // 80*65
    float* Vs = Ks + CMAX * KST;       // 80*65
    float* qs = Vs + CMAX * KST;       // 8*4*64
    float* ps = qs + 8 * 4 * HD;       // 8*4*80

    int g = blockIdx.x >> 2;
    int h = blockIdx.x & 3;
    int cnt = g_counts[g];
    int off = g_offsets[g];

    const float* base = g_qkv + (size_t)off * QKV3;
    for (int idx = threadIdx.x; idx < cnt * HD; idx += blockDim.x) {
        int m = idx >> 6, d = idx & 63;
        Ks[m * KST + d] = base[(size_t)m * QKV3 + E     + h * HD + d];
        Vs[m * KST + d] = base[(size_t)m * QKV3 + 2 * E + h * HD + d];
    }
    __syncthreads();

    int w = threadIdx.x >> 5, lane = threadIdx.x & 31;
    float* qw = qs + w * 4 * HD;
    float* pw = ps + w * 4 * CMAX;

    for (int q0 = w * 4; q0 < cnt; q0 += 32) {
#pragma unroll
        for (int qi = 0; qi < 4; qi++) {
            int qidx = q0 + qi;
            const float* qrow = base + (size_t)((qidx < cnt) ? qidx : q0) * QKV3 + h * HD;
            qw[qi * HD + lane]      = qrow[lane];
            qw[qi * HD + lane + 32] = qrow[lane + 32];
        }
        __syncwarp();

        float s[3][4];
        float mx[4] = {-1e30f, -1e30f, -1e30f, -1e30f};
#pragma unroll
        for (int mi = 0; mi < 3; mi++) {
            int m = lane + mi * 32;
            bool act = m < cnt;
            float a0 = 0.f, a1 = 0.f, a2 = 0.f, a3 = 0.f;
            const float* kr = Ks + m * KST;
            if (act) {
#pragma unroll
                for (int d4 = 0; d4 < 16; d4++) {
                    float k0 = kr[d4 * 4 + 0], k1 = kr[d4 * 4 + 1];
                    float k2 = kr[d4 * 4 + 2], k3 = kr[d4 * 4 + 3];
                    float4 v0 = *(const float4*)&qw[0 * HD + d4 * 4];
                    float4 v1 = *(const float4*)&qw[1 * HD + d4 * 4];
                    float4 v2 = *(const float4*)&qw[2 * HD + d4 * 4];
                    float4 v3 = *(const float4*)&qw[3 * HD + d4 * 4];
                    a0 += v0.x * k0 + v0.y * k1 + v0.z * k2 + v0.w * k3;
                    a1 += v1.x * k0 + v1.y * k1 + v1.z * k2 + v1.w * k3;
                    a2 += v2.x * k0 + v2.y * k1 + v2.z * k2 + v2.w * k3;
                    a3 += v3.x * k0 + v3.y * k1 + v3.z * k2 + v3.w * k3;
                }
            }
            s[mi][0] = act ? a0 * 0.125f : -1e30f;
            s[mi][1] = act ? a1 * 0.125f : -1e30f;
            s[mi][2] = act ? a2 * 0.125f : -1e30f;
            s[mi][3] = act ? a3 * 0.125f : -1e30f;
#pragma unroll
            for (int qi = 0; qi < 4; qi++) mx[qi] = fmaxf(mx[qi], s[mi][qi]);
        }
#pragma unroll
        for (int qi = 0; qi < 4; qi++)
#pragma unroll
            for (int o = 16; o; o >>= 1)
                mx[qi] = fmaxf(mx[qi], __shfl_xor_sync(0xFFFFFFFFu, mx[qi], o));

        float sum[4] = {0.f, 0.f, 0.f, 0.f};
#pragma unroll
        for (int mi = 0; mi < 3; mi++) {
            int m = lane + mi * 32;
            bool act = m < cnt;
#pragma unroll
            for (int qi = 0; qi < 4; qi++) {
                float e = act ? __expf(s[mi][qi] - mx[qi]) : 0.f;
                s[mi][qi] = e;
                sum[qi] += e;
            }
        }
#pragma unroll
        for (int qi = 0; qi < 4; qi++)
#pragma unroll
            for (int o = 16; o; o >>= 1)
                sum[qi] += __shfl_xor_sync(0xFFFFFFFFu, sum[qi], o);

        float inv[4];
#pragma unroll
        for (int qi = 0; qi < 4; qi++) inv[qi] = 1.f / sum[qi];

#pragma unroll
        for (int mi = 0; mi < 3; mi++) {
            int m = lane + mi * 32;
            if (m < cnt) {
#pragma unroll
                for (int qi = 0; qi < 4; qi++) pw[qi * CMAX + m] = s[mi][qi] * inv[qi];
            }
        }
        __syncwarp();

        float a[4][2];
#pragma unroll
        for (int qi = 0; qi < 4; qi++) { a[qi][0] = 0.f; a[qi][1] = 0.f; }
        for (int m = 0; m < cnt; m++) {
            float v0 = Vs[m * KST + lane];
            float v1 = Vs[m * KST + lane + 32];
#pragma unroll
            for (int qi = 0; qi < 4; qi++) {
                float pm = pw[qi * CMAX + m];
                a[qi][0] += pm * v0;
                a[qi][1] += pm * v1;
            }
        }
#pragma unroll
        for (int qi = 0; qi < 4; qi++) {
            int qidx = q0 + qi;
            if (qidx < cnt) {
                float* co = g_ctx + (size_t)(off + qidx) * E + h * HD;
                co[lane]      = a[qi][0];
                co[lane + 32] = a[qi][1];
            }
        }
        __syncwarp();
    }
}

__global__ void k_copytail(float* __restrict__ dst, const float* __restrict__ metal, int n) {
    int i = blockIdx.x * blockDim.x + threadIdx.x;
    if (i < n && i < B_GRAPHS * DM) dst[i] = metal[i];
}

// ---------------- launch ----------------
extern "C" void kernel_launch(void* const* d_in, const int* in_sizes, int n_in,
                              void* d_out, int out_size) {
    const float* x      = (const float*)d_in[0];
    const float* metal  = (const float*)d_in[1];
    const float* in_w   = (const float*)d_in[2];
    const float* in_b   = (const float*)d_in[3];
    const float* outp_w = (const float*)d_in[4];
    const float* outp_b = (const float*)d_in[5];
    const float* w_out  = (const float*)d_in[6];
    const float* b_out  = (const float*)d_in[7];
    const void*  batch  = d_in[8];
    int N = in_sizes[0] / DX;
    float* out = (float*)d_out;

    const int SMEM_G   = 32768 * 4 + 4 * 4096 * 4 + 512;   // sAf + sB ring + srcm
    const int SMEM_ATT = (2 * CMAX * KST + 8 * 4 * HD + 8 * 4 * CMAX) * 4;

    cudaFuncSetAttribute(k_gemm1_tc, cudaFuncAttributeMaxDynamicSharedMemorySize, SMEM_G);
    cudaFuncSetAttribute(k_gemm2_tc, cudaFuncAttributeMaxDynamicSharedMemorySize, SMEM_G);
    cudaFuncSetAttribute(k_attn,     cudaFuncAttributeMaxDynamicSharedMemorySize, SMEM_ATT);

    k_init<<<(B_GRAPHS + 255) / 256, 256>>>();
    k_detect<<<64, 256>>>(batch, N);
    k_wprep1<<<96, 256>>>(in_w);

    int nblk = (N + 127) / 128;
    k_gemm1_tc<<<nblk, GT_THREADS, SMEM_G>>>(x, metal, in_b, batch, N);

    k_counts<<<(N + 255) / 256, 256>>>(batch, N);
    k_scan<<<1, 1024>>>();
    k_rowrank<<<LMAX, 1024>>>();
    k_colprefix<<<1, 32>>>();
    k_dest<<<(N + 255) / 256, 256>>>(batch, N);
    k_w2<<<E, E>>>(w_out, outp_w);
    k_b2<<<1, E>>>(w_out, outp_b, b_out);
    k_wprep2<<<32, 256>>>();

    k_attn<<<B_GRAPHS * H, 256, SMEM_ATT>>>();

    k_gemm2_tc<<<nblk, GT_THREADS, SMEM_G>>>(out, N);

    long long tail = (long long)out_size - (long long)N * E;
    if (tail > 0) {
        k_copytail<<<((int)tail + 255) / 256, 256>>>(out + (size_t)N * E, metal, (int)tail);
    }
}